// round 13
// baseline (speedup 1.0000x reference)
#include <cuda_runtime.h>
#include <math.h>
#include <math_constants.h>

#define FULL 0xFFFFFFFFu
#define MAXN 20000
#define TM 32
#define TN 64
#define NSPLIT 4
#define LDA 132
#define LDCC 66
#define MAXBLK 625   /* ceil(MAXN/TM) */
#define SEG 1024
#define SMEM_MAIN ((TM*LDA + TN*LDA + TM*LDCC) * 4)

// ---------------- device scratch (no allocations allowed) ----------------
__device__ int   g_bm0[100000];            // membership stamp: users_cart
__device__ int   g_bm1[100000];            // membership stamp: users_purchase
__device__ int   g_common[3][MAXN];        // compacted common user ids per pair
__device__ int   g_N[3];                   // common sizes
__device__ int   g_any32;                  // nonzero odd 32-bit word seen => int32 input
__device__ int   g_gen;                    // generation counter (replay-safe bitmap reset)
__device__ int   g_cnt[3][32];             // per-segment match counts
__device__ float g_zs[3u * MAXN * 128];    // normalized strong embeddings (pre-scaled by 1/tau)
__device__ float g_zw[3u * MAXN * 128];    // normalized weak embeddings
__device__ float g_part[3u * MAXN * NSPLIT * 32];  // per-split sorted top-32 per row
__device__ float g_pos[3][MAXN];           // positive logit per row
__device__ float g_rowloss[3][MAXN];       // per-row loss

__device__ __forceinline__ int readu(const void* p, int i, int is64) {
    return is64 ? (int)((const long long*)p)[i] : ((const int*)p)[i];
}

// fp32 -> (tf32 hi, fp32 lo) split; lo passed raw (HW truncation error ~2^-22 rel)
__device__ __forceinline__ void split_tf32(float v, unsigned& hi, unsigned& lo) {
    unsigned h;
    asm("cvt.rna.tf32.f32 %0, %1;" : "=r"(h) : "f"(v));
    hi = h;
    lo = __float_as_uint(v - __uint_as_float(h));
}

// D += A(m16k8,tf32) * B(k8n8,tf32), fp32 accumulate
__device__ __forceinline__ void mma8(float* c, const unsigned* a, const unsigned* b) {
    asm volatile(
        "mma.sync.aligned.m16n8k8.row.col.f32.tf32.tf32.f32 "
        "{%0,%1,%2,%3}, {%4,%5,%6,%7}, {%8,%9}, {%0,%1,%2,%3};"
        : "+f"(c[0]), "+f"(c[1]), "+f"(c[2]), "+f"(c[3])
        : "r"(a[0]), "r"(a[1]), "r"(a[2]), "r"(a[3]), "r"(b[0]), "r"(b[1]));
}

// exact top-32 of (a ∪ b): a, b sorted ascending across lanes; result sorted ascending.
__device__ __forceinline__ float bitonic_merge32(float a, float b, int lane) {
    float br = __shfl_sync(FULL, b, 31 - lane);
    float c = fmaxf(a, br);                  // bitonic sequence, = top-32 multiset
    #pragma unroll
    for (int d = 16; d; d >>= 1) {
        float o = __shfl_xor_sync(FULL, c, d);
        c = ((lane & d) == 0) ? fminf(c, o) : fmaxf(c, o);
    }
    return c;
}

__device__ __forceinline__ void seg_decode(int b, int nseg0, int nseg1,
                                           const void* uv, int nv,
                                           const void* uc, int nc,
                                           int& p, int& seg, const void*& src,
                                           int& n, const int*& bm) {
    if (b < nseg0)               { p = 0; seg = b;                 src = uv; n = nv; bm = g_bm0; }
    else if (b < nseg0 + nseg1)  { p = 1; seg = b - nseg0;         src = uc; n = nc; bm = g_bm1; }
    else                         { p = 2; seg = b - nseg0 - nseg1; src = uv; n = nv; bm = g_bm1; }
}

// ---------------- K1: dtype detection + generation bump (single block) ----------------
__global__ void detect_kernel(const unsigned* w, int n) {
    __shared__ int s_or;
    if (threadIdx.x == 0) s_or = 0;
    __syncthreads();
    unsigned acc = 0;
    for (int j = 2 * threadIdx.x + 1; j < n; j += 2048) acc |= w[j];
    if (acc) atomicOr(&s_or, 1);
    __syncthreads();
    if (threadIdx.x == 0) {
        g_any32 = s_or;
        g_gen = g_gen + 1;     // new generation invalidates all old bitmap stamps
    }
}

// ---------------- K2: scatter membership stamps ----------------
__global__ void scatter_kernel(const void* uc, int nc,
                               const void* up, int np) {
    int is64 = (g_any32 == 0);
    int gen = g_gen;
    int i = blockIdx.x * blockDim.x + threadIdx.x;
    if (i < nc) {
        int v = readu(uc, i, is64);
        if (v >= 0 && v < 100000) g_bm0[v] = gen;
    } else if (i < nc + np) {
        int v = readu(up, i - nc, is64);
        if (v >= 0 && v < 100000) g_bm1[v] = gen;
    }
}

// ---------------- K3a: per-segment match counts ----------------
__global__ void count_kernel(const void* uv, int nv, const void* uc, int nc,
                             int nseg0, int nseg1) {
    int is64 = (g_any32 == 0);
    int gen = g_gen;
    int p, seg, n; const void* src; const int* bm;
    seg_decode(blockIdx.x, nseg0, nseg1, uv, nv, uc, nc, p, seg, src, n, bm);
    __shared__ int wc[32];
    int tid = threadIdx.x, lane = tid & 31, w = tid >> 5;
    int i = seg * SEG + tid;
    int flag = 0;
    if (i < n) {
        int v = readu(src, i, is64);
        if (v >= 0 && v < 100000) flag = (bm[v] == gen);
    }
    unsigned m = __ballot_sync(FULL, flag);
    if (lane == 0) wc[w] = __popc(m);
    __syncthreads();
    if (tid == 0) {
        int s = 0;
        #pragma unroll
        for (int k = 0; k < 32; k++) s += wc[k];
        g_cnt[p][seg] = s;
    }
}

// ---------------- K3b: stable scatter into g_common (prefix computed in-block) ----------------
__global__ void scatter2_kernel(const void* uv, int nv, const void* uc, int nc,
                                int nseg0, int nseg1) {
    int is64 = (g_any32 == 0);
    int gen = g_gen;
    int p, seg, n; const void* src; const int* bm;
    seg_decode(blockIdx.x, nseg0, nseg1, uv, nv, uc, nc, p, seg, src, n, bm);
    __shared__ int woff[32];
    __shared__ int segbase;
    int tid = threadIdx.x, lane = tid & 31, w = tid >> 5;
    int i = seg * SEG + tid;
    int val = 0, flag = 0;
    if (i < n) {
        val = readu(src, i, is64);
        if (val >= 0 && val < 100000) flag = (bm[val] == gen);
    }
    unsigned m = __ballot_sync(FULL, flag);
    if (lane == 0) woff[w] = __popc(m);
    if (tid == 0) {
        int nseg = (p == 1) ? nseg1 : nseg0;
        int b = 0, tot = 0;
        for (int s2 = 0; s2 < nseg; s2++) {
            if (s2 < seg) b += g_cnt[p][s2];
            tot += g_cnt[p][s2];
        }
        segbase = b;
        if (seg == 0) g_N[p] = (tot > MAXN) ? MAXN : tot;
    }
    __syncthreads();
    if (w == 0) {
        int v = woff[lane], inc = v;
        #pragma unroll
        for (int o = 1; o < 32; o <<= 1) {
            int t = __shfl_up_sync(FULL, inc, o);
            if (lane >= o) inc += t;
        }
        woff[lane] = inc - v;
    }
    __syncthreads();
    if (flag) {
        int pos = segbase + woff[w] + __popc(m & ((1u << lane) - 1));
        if (pos < MAXN) g_common[p][pos] = val;
    }
}

// ---------------- K4: gather + L2-normalize (warp per (pair,row)) ----------------
__global__ void gather_norm_kernel(const float* __restrict__ ev,
                                   const float* __restrict__ ec,
                                   const float* __restrict__ ep) {
    int wgid = blockIdx.x * 8 + (threadIdx.x >> 5);
    int lane = threadIdx.x & 31;
    int p = wgid / MAXN;
    if (p >= 3) return;
    int row = wgid - p * MAXN;
    int N = g_N[p];
    if (row >= N) return;
    int u = g_common[p][row];
    const float* ew = (p == 1) ? ec : ev;   // weak:  view, cart, view
    const float* es = (p == 0) ? ec : ep;   // strong: cart, purchase, purchase
    size_t off = (size_t)u * 128 + lane * 4;

    float4 a = *(const float4*)(ew + off);
    float ss = a.x * a.x + a.y * a.y + a.z * a.z + a.w * a.w;
    #pragma unroll
    for (int o = 16; o; o >>= 1) ss += __shfl_xor_sync(FULL, ss, o);
    float inv = 1.0f / fmaxf(sqrtf(ss), 1e-12f);
    float4 o4 = make_float4(a.x * inv, a.y * inv, a.z * inv, a.w * inv);
    *(float4*)(g_zw + ((size_t)p * MAXN + row) * 128 + lane * 4) = o4;

    float4 b = *(const float4*)(es + off);
    float s2 = b.x * b.x + b.y * b.y + b.z * b.z + b.w * b.w;
    #pragma unroll
    for (int o = 16; o; o >>= 1) s2 += __shfl_xor_sync(FULL, s2, o);
    float inv2 = 10.0f / fmaxf(sqrtf(s2), 1e-12f);   // fold 1/tau into strong side
    float4 o5 = make_float4(b.x * inv2, b.y * inv2, b.z * inv2, b.w * inv2);
    *(float4*)(g_zs + ((size_t)p * MAXN + row) * 128 + lane * 4) = o5;
}

// ---------------- K5: split-TF32 tensor-core GEMM + streaming partial top-32 ----------------
__global__ void __launch_bounds__(256, 3) main_kernel() {
    extern __shared__ __align__(16) float smem[];
    float* Ash = smem;                       // [TM][LDA]
    float* Bsh = Ash + TM * LDA;             // [TN][LDA]
    float* Csh = Bsh + TN * LDA;             // [TM][LDCC]

    int p = blockIdx.z;
    int s = blockIdx.y;
    int N = g_N[p];
    int row0 = blockIdx.x * TM;
    if (N < 4 || row0 >= N) return;

    const float* zs = g_zs + (size_t)p * MAXN * 128;
    const float* zw = g_zw + (size_t)p * MAXN * 128;

    int tid = threadIdx.x;
    int lane = tid & 31, wid = tid >> 5;
    int gid = lane >> 2, tig = lane & 3;     // mma groupID / threadID-in-group
    int wm = wid & 1, wn = wid >> 1;         // 2 m-warps x 4 n-warps
    int am = wm * 16;                        // warp's A row base
    int bn = wn * 16;                        // warp's B col base

    // load A tile (32 rows x 128)
    #pragma unroll
    for (int it = 0; it < 4; it++) {
        int idx = it * 256 + tid;
        int r = idx >> 5, c4 = (idx & 31) << 2;
        int gr = row0 + r;
        float4 v = make_float4(0.f, 0.f, 0.f, 0.f);
        if (gr < N) v = *(const float4*)(zs + (size_t)gr * 128 + c4);
        *(float4*)(Ash + r * LDA + c4) = v;
    }

    // per-row partial top-32: sorted ascending across lanes
    float tv[4];
    tv[0] = tv[1] = tv[2] = tv[3] = -CUDART_INF_F;

    const float* Abase = Ash + (am + gid) * LDA + tig;
    const float* Bbase = Bsh + (bn + gid) * LDA + tig;

    for (int jt = s * TN; jt < N; jt += NSPLIT * TN) {
        // load B tile (64 cols x 128)
        #pragma unroll
        for (int it = 0; it < 8; it++) {
            int idx = it * 256 + tid;
            int r = idx >> 5, c4 = (idx & 31) << 2;
            int gc = jt + r;
            float4 v = make_float4(0.f, 0.f, 0.f, 0.f);
            if (gc < N) v = *(const float4*)(zw + (size_t)gc * 128 + c4);
            *(float4*)(Bsh + r * LDA + c4) = v;
        }
        __syncthreads();

        float cm[2][4], cc[2][4];
        #pragma unroll
        for (int nt = 0; nt < 2; nt++)
            #pragma unroll
            for (int i = 0; i < 4; i++) { cm[nt][i] = 0.f; cc[nt][i] = 0.f; }

        #pragma unroll 4
        for (int k = 0; k < 128; k += 8) {
            // A fragment: (g,t),(g+8,t),(g,t+4),(g+8,t+4)
            float a0 = Abase[k];
            float a1 = Abase[8 * LDA + k];
            float a2 = Abase[k + 4];
            float a3 = Abase[8 * LDA + k + 4];
            unsigned ahi[4], alo[4];
            split_tf32(a0, ahi[0], alo[0]);
            split_tf32(a1, ahi[1], alo[1]);
            split_tf32(a2, ahi[2], alo[2]);
            split_tf32(a3, ahi[3], alo[3]);
            #pragma unroll
            for (int nt = 0; nt < 2; nt++) {
                // B fragment (col-major k8n8): (t, g), (t+4, g)
                float b0 = Bbase[nt * 8 * LDA + k];
                float b1 = Bbase[nt * 8 * LDA + k + 4];
                unsigned bhi[2], blo[2];
                split_tf32(b0, bhi[0], blo[0]);
                split_tf32(b1, bhi[1], blo[1]);
                mma8(cm[nt], ahi, bhi);   // hi*hi
                mma8(cc[nt], ahi, blo);   // hi*lo
                mma8(cc[nt], alo, bhi);   // lo*hi
            }
        }
        __syncthreads();   // all warps done reading Bsh; Csh safe to (re)write

        // write C: rows am+gid(+8), cols bn+nt*8+2*tig(+1)
        #pragma unroll
        for (int nt = 0; nt < 2; nt++) {
            int cb = bn + nt * 8 + 2 * tig;
            float2 lo2 = make_float2(cm[nt][0] + cc[nt][0], cm[nt][1] + cc[nt][1]);
            float2 hi2 = make_float2(cm[nt][2] + cc[nt][2], cm[nt][3] + cc[nt][3]);
            *(float2*)(Csh + (am + gid) * LDCC + cb)     = lo2;
            *(float2*)(Csh + (am + gid + 8) * LDCC + cb) = hi2;
        }
        __syncthreads();

        // ---- merge 64 candidates/row into per-row top-32; 4 rows interleaved for ILP ----
        float v0[4], v1[4], thr[4];
        bool  act[4];
        #pragma unroll
        for (int rr = 0; rr < 4; rr++) {
            int r = wid * 4 + rr;
            int rg = row0 + r;
            bool valid = (rg < N);
            float a = -CUDART_INF_F, b = -CUDART_INF_F;
            if (valid) {
                a = Csh[r * LDCC + lane];
                b = Csh[r * LDCC + 32 + lane];
                int j0 = jt + lane, j1 = jt + 32 + lane;
                if (j0 >= N) a = -CUDART_INF_F;
                else if (j0 == rg) { g_pos[p][rg] = a; a = -CUDART_INF_F; }
                if (j1 >= N) b = -CUDART_INF_F;
                else if (j1 == rg) { g_pos[p][rg] = b; b = -CUDART_INF_F; }
            }
            v0[rr] = a; v1[rr] = b;
            thr[rr] = __shfl_sync(FULL, tv[rr], 0);
            act[rr] = valid;
        }
        while (act[0] | act[1] | act[2] | act[3]) {
            #pragma unroll
            for (int rr = 0; rr < 4; rr++) {
                unsigned m0 = __ballot_sync(FULL, act[rr] && (v0[rr] > thr[rr]));
                unsigned m1 = __ballot_sync(FULL, act[rr] && (v1[rr] > thr[rr]));
                bool has = (m0 | m1) != 0u;
                int sl = m0 ? (__ffs(m0) - 1) : (m1 ? (__ffs(m1) - 1) : 0);
                float v = m0 ? __shfl_sync(FULL, v0[rr], sl)
                             : __shfl_sync(FULL, v1[rr], sl);
                if (has && lane == sl) {
                    if (m0) v0[rr] = -CUDART_INF_F; else v1[rr] = -CUDART_INF_F;
                }
                float t = tv[rr];
                float an = __shfl_down_sync(FULL, t, 1);      // t[lane+1]
                if (lane == 31) an = CUDART_INF_F;
                float s1 = __shfl_sync(FULL, an, 0);          // old 2nd-smallest
                if (has) {
                    tv[rr]  = (an <= v) ? an : (t <= v ? v : t);
                    thr[rr] = fminf(s1, v);                   // new min of list
                }
                act[rr] = has;
            }
        }
        __syncthreads();
    }

    // write partial top-32 (lane-distributed, sorted ascending)
    #pragma unroll
    for (int rr = 0; rr < 4; rr++) {
        int rg = row0 + wid * 4 + rr;
        if (rg < N)
            g_part[(((size_t)p * MAXN + rg) * NSPLIT + s) * 32 + lane] = tv[rr];
    }
}

// ---------------- K5b: bitonic merge of partial top-32 sets + LSE (warp per row) ----------------
__global__ void merge_kernel() {
    int wgid = blockIdx.x * 8 + (threadIdx.x >> 5);
    int lane = threadIdx.x & 31;
    int p = wgid / MAXN;
    if (p >= 3) return;
    int row = wgid - p * MAXN;
    int N = g_N[p];
    if (N < 4 || row >= N) return;

    float v[NSPLIT];
    #pragma unroll
    for (int s = 0; s < NSPLIT; s++)
        v[s] = g_part[(((size_t)p * MAXN + row) * NSPLIT + s) * 32 + lane];
    float pos = g_pos[p][row];

    // exact top-32 of the union via log-depth bitonic max-merges
    float m01 = bitonic_merge32(v[0], v[1], lane);
    float m23 = bitonic_merge32(v[2], v[3], lane);
    float top = bitonic_merge32(m01, m23, lane);    // sorted ascending

    float M = fmaxf(pos, __shfl_sync(FULL, top, 31));
    float e = (top > -CUDART_INF_F) ? expf(top - M) : 0.0f;
    #pragma unroll
    for (int o = 16; o; o >>= 1) e += __shfl_xor_sync(FULL, e, o);
    if (lane == 0)
        g_rowloss[p][row] = logf(e + expf(pos - M)) + M - pos;
}

// ---------------- K6: deterministic final reduction ----------------
__global__ void finalize_kernel(float* out) {
    __shared__ float red[768];
    int tid = threadIdx.x;
    int p = tid >> 8, t = tid & 255;
    int n = g_N[p];
    float s = 0.f;
    if (n >= 4)
        for (int i = t; i < n; i += 256) s += g_rowloss[p][i];
    red[tid] = s;
    __syncthreads();
    #pragma unroll
    for (int off = 128; off; off >>= 1) {
        if (t < off) red[tid] += red[tid + off];
        __syncthreads();
    }
    if (tid == 0) {
        const float wgt[3] = {0.2f, 1.0f, 1.0f};
        float loss = 0.f;
        #pragma unroll
        for (int q = 0; q < 3; q++) {
            int nq = g_N[q];
            if (nq >= 4) loss += wgt[q] * (red[q * 256] / (float)nq);
        }
        out[0] = loss;
    }
}

// ---------------- host launcher (graph-capturable) ----------------
extern "C" void kernel_launch(void* const* d_in, const int* in_sizes, int n_in,
                              void* d_out, int out_size) {
    const float* ev = (const float*)d_in[0];
    const float* ec = (const float*)d_in[1];
    const float* ep = (const float*)d_in[2];
    const void*  uv = d_in[3];
    const void*  uc = d_in[4];
    const void*  up = d_in[5];
    int nv = in_sizes[3], nc = in_sizes[4], np = in_sizes[5];

    int nseg0 = (nv + SEG - 1) / SEG;
    int nseg1 = (nc + SEG - 1) / SEG;
    int nblk = nseg0 + nseg1 + nseg0;

    cudaFuncSetAttribute(main_kernel, cudaFuncAttributeMaxDynamicSharedMemorySize, SMEM_MAIN);

    detect_kernel<<<1, 1024>>>((const unsigned*)uv, nv);
    scatter_kernel<<<(nc + np + 255) / 256, 256>>>(uc, nc, up, np);
    count_kernel<<<nblk, 1024>>>(uv, nv, uc, nc, nseg0, nseg1);
    scatter2_kernel<<<nblk, 1024>>>(uv, nv, uc, nc, nseg0, nseg1);
    gather_norm_kernel<<<(3 * MAXN + 7) / 8, 256>>>(ev, ec, ep);
    main_kernel<<<dim3(MAXBLK, NSPLIT, 3), 256, SMEM_MAIN>>>();
    merge_kernel<<<(3 * MAXN + 7) / 8, 256>>>();
    finalize_kernel<<<1, 768>>>((float*)d_out);
}

// round 14
// speedup vs baseline: 1.8343x; 1.8343x over previous
#include <cuda_runtime.h>
#include <math.h>
#include <math_constants.h>

#define FULL 0xFFFFFFFFu
#define MAXN 20000
#define TM 32
#define TN 64
#define NSPLIT 4
#define LDA 132
#define LDCC 66
#define MAXBLK 625   /* ceil(MAXN/TM) */
#define SEG 1024
#define SMEM_MAIN ((TM*LDA + TN*LDA + TM*LDCC) * 4)

// ---------------- device scratch (no allocations allowed) ----------------
__device__ int   g_bm0[100000];            // membership stamp: users_cart
__device__ int   g_bm1[100000];            // membership stamp: users_purchase
__device__ int   g_common[3][MAXN];        // compacted common user ids per pair
__device__ int   g_N[3];                   // common sizes
__device__ int   g_any32;                  // nonzero odd 32-bit word seen => int32 input
__device__ int   g_gen;                    // generation counter (replay-safe bitmap reset)
__device__ int   g_cnt[3][32];             // per-segment match counts
__device__ float g_zs[3u * MAXN * 128];    // normalized strong embeddings (pre-scaled by 1/tau)
__device__ float g_zw[3u * MAXN * 128];    // normalized weak embeddings
__device__ float g_part[3u * MAXN * NSPLIT * 32];  // per-split sorted top-32 per row
__device__ float g_pos[3][MAXN];           // positive logit per row
__device__ float g_rowloss[3][MAXN];       // per-row loss

__device__ __forceinline__ int readu(const void* p, int i, int is64) {
    return is64 ? (int)((const long long*)p)[i] : ((const int*)p)[i];
}

// fp32 -> (tf32 hi, fp32 lo) split; lo passed raw (HW truncation error ~2^-22 rel)
__device__ __forceinline__ void split_tf32(float v, unsigned& hi, unsigned& lo) {
    unsigned h;
    asm("cvt.rna.tf32.f32 %0, %1;" : "=r"(h) : "f"(v));
    hi = h;
    lo = __float_as_uint(v - __uint_as_float(h));
}

// D += A(m16k8,tf32) * B(k8n8,tf32), fp32 accumulate
__device__ __forceinline__ void mma8(float* c, const unsigned* a, const unsigned* b) {
    asm volatile(
        "mma.sync.aligned.m16n8k8.row.col.f32.tf32.tf32.f32 "
        "{%0,%1,%2,%3}, {%4,%5,%6,%7}, {%8,%9}, {%0,%1,%2,%3};"
        : "+f"(c[0]), "+f"(c[1]), "+f"(c[2]), "+f"(c[3])
        : "r"(a[0]), "r"(a[1]), "r"(a[2]), "r"(a[3]), "r"(b[0]), "r"(b[1]));
}

// full bitonic sort of one value per lane, ascending across lanes (15 steps)
__device__ __forceinline__ float bitonic_sort32(float v, int lane) {
    #pragma unroll
    for (int k = 2; k <= 32; k <<= 1) {
        #pragma unroll
        for (int j = k >> 1; j > 0; j >>= 1) {
            float o = __shfl_xor_sync(FULL, v, j);
            bool up = ((lane & k) == 0);          // k=32: always ascending
            bool keepmin = (((lane & j) == 0) == up);
            v = keepmin ? fminf(v, o) : fmaxf(v, o);
        }
    }
    return v;
}

// exact top-32 of (a ∪ b): a, b sorted ascending across lanes; result sorted ascending.
__device__ __forceinline__ float bitonic_merge32(float a, float b, int lane) {
    float br = __shfl_sync(FULL, b, 31 - lane);
    float c = fmaxf(a, br);                  // bitonic sequence, = top-32 multiset
    #pragma unroll
    for (int d = 16; d; d >>= 1) {
        float o = __shfl_xor_sync(FULL, c, d);
        c = ((lane & d) == 0) ? fminf(c, o) : fmaxf(c, o);
    }
    return c;
}

__device__ __forceinline__ void seg_decode(int b, int nseg0, int nseg1,
                                           const void* uv, int nv,
                                           const void* uc, int nc,
                                           int& p, int& seg, const void*& src,
                                           int& n, const int*& bm) {
    if (b < nseg0)               { p = 0; seg = b;                 src = uv; n = nv; bm = g_bm0; }
    else if (b < nseg0 + nseg1)  { p = 1; seg = b - nseg0;         src = uc; n = nc; bm = g_bm1; }
    else                         { p = 2; seg = b - nseg0 - nseg1; src = uv; n = nv; bm = g_bm1; }
}

// ---------------- K1: dtype detection + generation bump (single block) ----------------
__global__ void detect_kernel(const unsigned* w, int n) {
    __shared__ int s_or;
    if (threadIdx.x == 0) s_or = 0;
    __syncthreads();
    unsigned acc = 0;
    for (int j = 2 * threadIdx.x + 1; j < n; j += 2048) acc |= w[j];
    if (acc) atomicOr(&s_or, 1);
    __syncthreads();
    if (threadIdx.x == 0) {
        g_any32 = s_or;
        g_gen = g_gen + 1;     // new generation invalidates all old bitmap stamps
    }
}

// ---------------- K2: scatter membership stamps ----------------
__global__ void scatter_kernel(const void* uc, int nc,
                               const void* up, int np) {
    int is64 = (g_any32 == 0);
    int gen = g_gen;
    int i = blockIdx.x * blockDim.x + threadIdx.x;
    if (i < nc) {
        int v = readu(uc, i, is64);
        if (v >= 0 && v < 100000) g_bm0[v] = gen;
    } else if (i < nc + np) {
        int v = readu(up, i - nc, is64);
        if (v >= 0 && v < 100000) g_bm1[v] = gen;
    }
}

// ---------------- K3a: per-segment match counts ----------------
__global__ void count_kernel(const void* uv, int nv, const void* uc, int nc,
                             int nseg0, int nseg1) {
    int is64 = (g_any32 == 0);
    int gen = g_gen;
    int p, seg, n; const void* src; const int* bm;
    seg_decode(blockIdx.x, nseg0, nseg1, uv, nv, uc, nc, p, seg, src, n, bm);
    __shared__ int wc[32];
    int tid = threadIdx.x, lane = tid & 31, w = tid >> 5;
    int i = seg * SEG + tid;
    int flag = 0;
    if (i < n) {
        int v = readu(src, i, is64);
        if (v >= 0 && v < 100000) flag = (bm[v] == gen);
    }
    unsigned m = __ballot_sync(FULL, flag);
    if (lane == 0) wc[w] = __popc(m);
    __syncthreads();
    if (tid == 0) {
        int s = 0;
        #pragma unroll
        for (int k = 0; k < 32; k++) s += wc[k];
        g_cnt[p][seg] = s;
    }
}

// ---------------- K3b: stable scatter into g_common (prefix computed in-block) ----------------
__global__ void scatter2_kernel(const void* uv, int nv, const void* uc, int nc,
                                int nseg0, int nseg1) {
    int is64 = (g_any32 == 0);
    int gen = g_gen;
    int p, seg, n; const void* src; const int* bm;
    seg_decode(blockIdx.x, nseg0, nseg1, uv, nv, uc, nc, p, seg, src, n, bm);
    __shared__ int woff[32];
    __shared__ int segbase;
    int tid = threadIdx.x, lane = tid & 31, w = tid >> 5;
    int i = seg * SEG + tid;
    int val = 0, flag = 0;
    if (i < n) {
        val = readu(src, i, is64);
        if (val >= 0 && val < 100000) flag = (bm[val] == gen);
    }
    unsigned m = __ballot_sync(FULL, flag);
    if (lane == 0) woff[w] = __popc(m);
    if (tid == 0) {
        int nseg = (p == 1) ? nseg1 : nseg0;
        int b = 0, tot = 0;
        for (int s2 = 0; s2 < nseg; s2++) {
            if (s2 < seg) b += g_cnt[p][s2];
            tot += g_cnt[p][s2];
        }
        segbase = b;
        if (seg == 0) g_N[p] = (tot > MAXN) ? MAXN : tot;
    }
    __syncthreads();
    if (w == 0) {
        int v = woff[lane], inc = v;
        #pragma unroll
        for (int o = 1; o < 32; o <<= 1) {
            int t = __shfl_up_sync(FULL, inc, o);
            if (lane >= o) inc += t;
        }
        woff[lane] = inc - v;
    }
    __syncthreads();
    if (flag) {
        int pos = segbase + woff[w] + __popc(m & ((1u << lane) - 1));
        if (pos < MAXN) g_common[p][pos] = val;
    }
}

// ---------------- K4: gather + L2-normalize (warp per (pair,row)) ----------------
__global__ void gather_norm_kernel(const float* __restrict__ ev,
                                   const float* __restrict__ ec,
                                   const float* __restrict__ ep) {
    int wgid = blockIdx.x * 8 + (threadIdx.x >> 5);
    int lane = threadIdx.x & 31;
    int p = wgid / MAXN;
    if (p >= 3) return;
    int row = wgid - p * MAXN;
    int N = g_N[p];
    if (row >= N) return;
    int u = g_common[p][row];
    const float* ew = (p == 1) ? ec : ev;   // weak:  view, cart, view
    const float* es = (p == 0) ? ec : ep;   // strong: cart, purchase, purchase
    size_t off = (size_t)u * 128 + lane * 4;

    float4 a = *(const float4*)(ew + off);
    float ss = a.x * a.x + a.y * a.y + a.z * a.z + a.w * a.w;
    #pragma unroll
    for (int o = 16; o; o >>= 1) ss += __shfl_xor_sync(FULL, ss, o);
    float inv = 1.0f / fmaxf(sqrtf(ss), 1e-12f);
    float4 o4 = make_float4(a.x * inv, a.y * inv, a.z * inv, a.w * inv);
    *(float4*)(g_zw + ((size_t)p * MAXN + row) * 128 + lane * 4) = o4;

    float4 b = *(const float4*)(es + off);
    float s2 = b.x * b.x + b.y * b.y + b.z * b.z + b.w * b.w;
    #pragma unroll
    for (int o = 16; o; o >>= 1) s2 += __shfl_xor_sync(FULL, s2, o);
    float inv2 = 10.0f / fmaxf(sqrtf(s2), 1e-12f);   // fold 1/tau into strong side
    float4 o5 = make_float4(b.x * inv2, b.y * inv2, b.z * inv2, b.w * inv2);
    *(float4*)(g_zs + ((size_t)p * MAXN + row) * 128 + lane * 4) = o5;
}

// ---------------- K5: split-TF32 tensor-core GEMM + batched bitonic top-32 ----------------
__global__ void __launch_bounds__(256, 3) main_kernel() {
    extern __shared__ __align__(16) float smem[];
    float* Ash = smem;                       // [TM][LDA]
    float* Bsh = Ash + TM * LDA;             // [TN][LDA]
    float* Csh = Bsh + TN * LDA;             // [TM][LDCC]

    int p = blockIdx.z;
    int s = blockIdx.y;
    int N = g_N[p];
    int row0 = blockIdx.x * TM;
    if (N < 4 || row0 >= N) return;

    const float* zs = g_zs + (size_t)p * MAXN * 128;
    const float* zw = g_zw + (size_t)p * MAXN * 128;

    int tid = threadIdx.x;
    int lane = tid & 31, wid = tid >> 5;
    int gid = lane >> 2, tig = lane & 3;     // mma groupID / threadID-in-group
    int wm = wid & 1, wn = wid >> 1;         // 2 m-warps x 4 n-warps
    int am = wm * 16;                        // warp's A row base
    int bn = wn * 16;                        // warp's B col base

    // load A tile (32 rows x 128)
    #pragma unroll
    for (int it = 0; it < 4; it++) {
        int idx = it * 256 + tid;
        int r = idx >> 5, c4 = (idx & 31) << 2;
        int gr = row0 + r;
        float4 v = make_float4(0.f, 0.f, 0.f, 0.f);
        if (gr < N) v = *(const float4*)(zs + (size_t)gr * 128 + c4);
        *(float4*)(Ash + r * LDA + c4) = v;
    }

    // per-row partial top-32: sorted ascending across lanes
    float tv[4];
    tv[0] = tv[1] = tv[2] = tv[3] = -CUDART_INF_F;

    const float* Abase = Ash + (am + gid) * LDA + tig;
    const float* Bbase = Bsh + (bn + gid) * LDA + tig;

    for (int jt = s * TN; jt < N; jt += NSPLIT * TN) {
        // load B tile (64 cols x 128)
        #pragma unroll
        for (int it = 0; it < 8; it++) {
            int idx = it * 256 + tid;
            int r = idx >> 5, c4 = (idx & 31) << 2;
            int gc = jt + r;
            float4 v = make_float4(0.f, 0.f, 0.f, 0.f);
            if (gc < N) v = *(const float4*)(zw + (size_t)gc * 128 + c4);
            *(float4*)(Bsh + r * LDA + c4) = v;
        }
        __syncthreads();

        float cm[2][4], cc[2][4];
        #pragma unroll
        for (int nt = 0; nt < 2; nt++)
            #pragma unroll
            for (int i = 0; i < 4; i++) { cm[nt][i] = 0.f; cc[nt][i] = 0.f; }

        #pragma unroll 4
        for (int k = 0; k < 128; k += 8) {
            // A fragment: (g,t),(g+8,t),(g,t+4),(g+8,t+4)
            float a0 = Abase[k];
            float a1 = Abase[8 * LDA + k];
            float a2 = Abase[k + 4];
            float a3 = Abase[8 * LDA + k + 4];
            unsigned ahi[4], alo[4];
            split_tf32(a0, ahi[0], alo[0]);
            split_tf32(a1, ahi[1], alo[1]);
            split_tf32(a2, ahi[2], alo[2]);
            split_tf32(a3, ahi[3], alo[3]);
            #pragma unroll
            for (int nt = 0; nt < 2; nt++) {
                // B fragment (col-major k8n8): (t, g), (t+4, g)
                float b0 = Bbase[nt * 8 * LDA + k];
                float b1 = Bbase[nt * 8 * LDA + k + 4];
                unsigned bhi[2], blo[2];
                split_tf32(b0, bhi[0], blo[0]);
                split_tf32(b1, bhi[1], blo[1]);
                mma8(cm[nt], ahi, bhi);   // hi*hi
                mma8(cc[nt], ahi, blo);   // hi*lo
                mma8(cc[nt], alo, bhi);   // lo*hi
            }
        }
        __syncthreads();   // all warps done reading Bsh; Csh safe to (re)write

        // write C: rows am+gid(+8), cols bn+nt*8+2*tig(+1)
        #pragma unroll
        for (int nt = 0; nt < 2; nt++) {
            int cb = bn + nt * 8 + 2 * tig;
            float2 lo2 = make_float2(cm[nt][0] + cc[nt][0], cm[nt][1] + cc[nt][1]);
            float2 hi2 = make_float2(cm[nt][2] + cc[nt][2], cm[nt][3] + cc[nt][3]);
            *(float2*)(Csh + (am + gid) * LDCC + cb)     = lo2;
            *(float2*)(Csh + (am + gid + 8) * LDCC + cb) = hi2;
        }
        __syncthreads();

        // ---- batched merge: sort 64 candidates, fold into running top-32 ----
        // fixed-cost, divergence-free: 2 sorts (ILP) + 2 bitonic merges per row
        #pragma unroll
        for (int rr = 0; rr < 4; rr++) {
            int r = wid * 4 + rr;
            int rg = row0 + r;
            bool valid = (rg < N);                 // warp-uniform
            float a = -CUDART_INF_F, b = -CUDART_INF_F;
            if (valid) {
                a = Csh[r * LDCC + lane];
                b = Csh[r * LDCC + 32 + lane];
                int j0 = jt + lane, j1 = jt + 32 + lane;
                if (j0 >= N) a = -CUDART_INF_F;
                else if (j0 == rg) { g_pos[p][rg] = a; a = -CUDART_INF_F; }
                if (j1 >= N) b = -CUDART_INF_F;
                else if (j1 == rg) { g_pos[p][rg] = b; b = -CUDART_INF_F; }
                float as = bitonic_sort32(a, lane);
                float bs = bitonic_sort32(b, lane);
                float m  = bitonic_merge32(as, bs, lane);
                tv[rr]   = bitonic_merge32(tv[rr], m, lane);
            }
        }
        __syncthreads();
    }

    // write partial top-32 (lane-distributed, sorted ascending)
    #pragma unroll
    for (int rr = 0; rr < 4; rr++) {
        int rg = row0 + wid * 4 + rr;
        if (rg < N)
            g_part[(((size_t)p * MAXN + rg) * NSPLIT + s) * 32 + lane] = tv[rr];
    }
}

// ---------------- K5b: bitonic merge of partial top-32 sets + LSE (warp per row) ----------------
__global__ void merge_kernel() {
    int wgid = blockIdx.x * 8 + (threadIdx.x >> 5);
    int lane = threadIdx.x & 31;
    int p = wgid / MAXN;
    if (p >= 3) return;
    int row = wgid - p * MAXN;
    int N = g_N[p];
    if (N < 4 || row >= N) return;

    float v[NSPLIT];
    #pragma unroll
    for (int s = 0; s < NSPLIT; s++)
        v[s] = g_part[(((size_t)p * MAXN + row) * NSPLIT + s) * 32 + lane];
    float pos = g_pos[p][row];

    // exact top-32 of the union via log-depth bitonic max-merges
    float m01 = bitonic_merge32(v[0], v[1], lane);
    float m23 = bitonic_merge32(v[2], v[3], lane);
    float top = bitonic_merge32(m01, m23, lane);    // sorted ascending

    float M = fmaxf(pos, __shfl_sync(FULL, top, 31));
    float e = (top > -CUDART_INF_F) ? expf(top - M) : 0.0f;
    #pragma unroll
    for (int o = 16; o; o >>= 1) e += __shfl_xor_sync(FULL, e, o);
    if (lane == 0)
        g_rowloss[p][row] = logf(e + expf(pos - M)) + M - pos;
}

// ---------------- K6: deterministic final reduction ----------------
__global__ void finalize_kernel(float* out) {
    __shared__ float red[768];
    int tid = threadIdx.x;
    int p = tid >> 8, t = tid & 255;
    int n = g_N[p];
    float s = 0.f;
    if (n >= 4)
        for (int i = t; i < n; i += 256) s += g_rowloss[p][i];
    red[tid] = s;
    __syncthreads();
    #pragma unroll
    for (int off = 128; off; off >>= 1) {
        if (t < off) red[tid] += red[tid + off];
        __syncthreads();
    }
    if (tid == 0) {
        const float wgt[3] = {0.2f, 1.0f, 1.0f};
        float loss = 0.f;
        #pragma unroll
        for (int q = 0; q < 3; q++) {
            int nq = g_N[q];
            if (nq >= 4) loss += wgt[q] * (red[q * 256] / (float)nq);
        }
        out[0] = loss;
    }
}

// ---------------- host launcher (graph-capturable) ----------------
extern "C" void kernel_launch(void* const* d_in, const int* in_sizes, int n_in,
                              void* d_out, int out_size) {
    const float* ev = (const float*)d_in[0];
    const float* ec = (const float*)d_in[1];
    const float* ep = (const float*)d_in[2];
    const void*  uv = d_in[3];
    const void*  uc = d_in[4];
    const void*  up = d_in[5];
    int nv = in_sizes[3], nc = in_sizes[4], np = in_sizes[5];

    int nseg0 = (nv + SEG - 1) / SEG;
    int nseg1 = (nc + SEG - 1) / SEG;
    int nblk = nseg0 + nseg1 + nseg0;

    cudaFuncSetAttribute(main_kernel, cudaFuncAttributeMaxDynamicSharedMemorySize, SMEM_MAIN);

    detect_kernel<<<1, 1024>>>((const unsigned*)uv, nv);
    scatter_kernel<<<(nc + np + 255) / 256, 256>>>(uc, nc, up, np);
    count_kernel<<<nblk, 1024>>>(uv, nv, uc, nc, nseg0, nseg1);
    scatter2_kernel<<<nblk, 1024>>>(uv, nv, uc, nc, nseg0, nseg1);
    gather_norm_kernel<<<(3 * MAXN + 7) / 8, 256>>>(ev, ec, ep);
    main_kernel<<<dim3(MAXBLK, NSPLIT, 3), 256, SMEM_MAIN>>>();
    merge_kernel<<<(3 * MAXN + 7) / 8, 256>>>();
    finalize_kernel<<<1, 768>>>((float*)d_out);
}